// round 15
// baseline (speedup 1.0000x reference)
#include <cuda_runtime.h>
#include <cuda_fp16.h>
#include <math.h>
#include <stdint.h>

// Problem constants
#define B_  4
#define N_  4096
#define D_  1024
#define H_  16
#define DH_ 64
#define M_  (B_ * N_)          // 16384
#define MD_ ((size_t)M_ * D_)
#define DD_ ((size_t)D_ * D_)

// ---------------------------------------------------------------------------
// Scratch (__device__ globals; no allocation allowed)
// ---------------------------------------------------------------------------
__device__ __half g_qpl [MD_];           // q single fp16 plane
__device__ __half g_qspl[MD_];           // qs single fp16 plane
__device__ __half g_xkT [2 * MD_];       // Xk^T [b][c][n] fp16 (hi | lo)
__device__ __half g_xvT [2 * MD_];       // Xv^T
__device__ __half g_gpl [2 * 4 * DD_];   // G' fp16 planes (hi | lo)
__device__ __half g_wpl [3 * DD_];       // Wq hi, Wk hi, Wk lo
__device__ __half g_vtpl[4 * DD_];       // Vt single fp16 plane
__device__ float g_P[4 * DD_];           // P[b][hd][c']
__device__ float g_ctxm[(size_t)64 * 64 * 64];
__device__ float g_sk[4 * 1024], g_sv[4 * 1024];
__device__ float g_u [4 * 1024], g_w [4 * 1024];

// ---------------------------------------------------------------------------
// PTX helpers (plain sm_103-safe)
// ---------------------------------------------------------------------------
__device__ __forceinline__ uint32_t smem_u32(const void* p) {
    uint32_t a;
    asm("{ .reg .u64 t; cvta.to.shared.u64 t, %1; cvt.u32.u64 %0, t; }"
        : "=r"(a) : "l"(p));
    return a;
}

#define CPA16(dst, src) \
    asm volatile("cp.async.cg.shared.global [%0], [%1], 16;" :: "r"(dst), "l"(src))
#define CPCOMMIT() asm volatile("cp.async.commit_group;" ::: "memory")
#define CPWAIT1()  asm volatile("cp.async.wait_group 1;" ::: "memory")

#define LDSM4(r, addr) \
    asm volatile("ldmatrix.sync.aligned.m8n8.x4.shared.b16 {%0,%1,%2,%3}, [%4];" \
        : "=r"((r)[0]), "=r"((r)[1]), "=r"((r)[2]), "=r"((r)[3]) : "r"(addr))

#define MMA16816(acc, a, b0, b1) \
    asm volatile("mma.sync.aligned.m16n8k16.row.col.f32.f16.f16.f32 " \
        "{%0,%1,%2,%3}, {%4,%5,%6,%7}, {%8,%9}, {%0,%1,%2,%3};" \
        : "+f"((acc)[0]), "+f"((acc)[1]), "+f"((acc)[2]), "+f"((acc)[3]) \
        : "r"((a)[0]), "r"((a)[1]), "r"((a)[2]), "r"((a)[3]), "r"(b0), "r"(b1))

__device__ __forceinline__ void split1(float x, uint16_t& h, uint16_t& l) {
    __half hb = __float2half_rn(x);
    __half lb = __float2half_rn(x - __half2float(hb));
    h = __half_as_ushort(hb);
    l = __half_as_ushort(lb);
}

// ---------------------------------------------------------------------------
// Row-major split: fp32 -> hi (and optional lo) fp16 planes
// ---------------------------------------------------------------------------
__global__ __launch_bounds__(256)
void split_kernel(const float* __restrict__ in,
                  __half* __restrict__ hi,
                  __half* __restrict__ lo, int n4)
{
    int i = blockIdx.x * blockDim.x + threadIdx.x;
    int stride = gridDim.x * blockDim.x;
    for (; i < n4; i += stride) {
        float4 v = ((const float4*)in)[i];
        uint16_t h0,l0,h1,l1,h2,l2,h3,l3;
        split1(v.x,h0,l0); split1(v.y,h1,l1); split1(v.z,h2,l2); split1(v.w,h3,l3);
        uint2 hv;
        hv.x = (uint32_t)h0 | ((uint32_t)h1 << 16);
        hv.y = (uint32_t)h2 | ((uint32_t)h3 << 16);
        *(uint2*)(hi + 4 * (size_t)i) = hv;
        if (lo) {
            uint2 lv;
            lv.x = (uint32_t)l0 | ((uint32_t)l1 << 16);
            lv.y = (uint32_t)l2 | ((uint32_t)l3 << 16);
            *(uint2*)(lo + 4 * (size_t)i) = lv;
        }
    }
}

// ---------------------------------------------------------------------------
// Transposing split + fused column sum:
// x[b][n][c] fp32 -> planes [b][c][n] fp16 (hi, lo); s[b][c] += sum_n x
// ---------------------------------------------------------------------------
__global__ __launch_bounds__(256)
void splitT_kernel(const float* __restrict__ in,
                   __half* __restrict__ hi,
                   __half* __restrict__ lo,
                   float* __restrict__ s)
{
    __shared__ float t[32][33];
    const int n0 = blockIdx.x * 32;
    const int c0 = blockIdx.y * 32;
    const int b  = blockIdx.z;

    {
        int row = threadIdx.x >> 3;          // n-local
        int c4  = (threadIdx.x & 7) * 4;     // c-local
        float4 v = *(const float4*)(in + ((size_t)b * N_ + n0 + row) * D_ + c0 + c4);
        t[c4 + 0][row] = v.x; t[c4 + 1][row] = v.y;
        t[c4 + 2][row] = v.z; t[c4 + 3][row] = v.w;
    }
    __syncthreads();
    {
        int c  = threadIdx.x >> 3;           // c-local
        int n4 = (threadIdx.x & 7) * 4;      // n-local
        float v0 = t[c][n4 + 0], v1 = t[c][n4 + 1];
        float v2 = t[c][n4 + 2], v3 = t[c][n4 + 3];

        float sum = (v0 + v1) + (v2 + v3);
        sum += __shfl_xor_sync(0xffffffffu, sum, 1);
        sum += __shfl_xor_sync(0xffffffffu, sum, 2);
        sum += __shfl_xor_sync(0xffffffffu, sum, 4);
        if ((threadIdx.x & 7) == 0)
            atomicAdd(&s[b * D_ + c0 + c], sum);

        uint16_t h0,l0,h1,l1,h2,l2,h3,l3;
        split1(v0, h0, l0); split1(v1, h1, l1);
        split1(v2, h2, l2); split1(v3, h3, l3);
        uint2 hv, lv;
        hv.x = (uint32_t)h0 | ((uint32_t)h1 << 16);
        hv.y = (uint32_t)h2 | ((uint32_t)h3 << 16);
        lv.x = (uint32_t)l0 | ((uint32_t)l1 << 16);
        lv.y = (uint32_t)l2 | ((uint32_t)l3 << 16);
        size_t off = ((size_t)b * D_ + c0 + c) * N_ + n0 + n4;
        *(uint2*)(hi + off) = hv;
        *(uint2*)(lo + off) = lv;
    }
}

// u[b][r] = sum_c W[r][c] * s[b][c]
__global__ __launch_bounds__(256)
void matvec_k(const float* __restrict__ W, const float* __restrict__ s,
              float* __restrict__ u)
{
    const int b = blockIdx.x;
    const int r = blockIdx.y * 8 + (threadIdx.x >> 5);
    const int lane = threadIdx.x & 31;
    float sum = 0.f;
    for (int c = lane; c < D_; c += 32)
        sum += W[(size_t)r * D_ + c] * s[b * D_ + c];
#pragma unroll
    for (int off = 16; off > 0; off >>= 1)
        sum += __shfl_xor_sync(0xffffffffu, sum, off);
    if (lane == 0) u[b * D_ + r] = sum;
}

// ---------------------------------------------------------------------------
// fp16 mma.sync GEMM, CTA tile 128x128, 256 threads (8 warps: 4M x 2N),
// warp tile 32x64, BK=32, 3-stage cp.async pipeline (lookahead-1, single
// barrier), 2 CTAs/SM for full-chip utilization on small grids.
// <ASINGLE, BSINGLE>:
//   false,false: 3-term (Ah+Al)(Bh+Bl) minus AlBl   (Gram, P)
//   true, true : 1-term Ah*Bh                       (Q-proj, out)
// Output fp32 OR fp16 plane(s) (cSingle: hi only).
// Optional fused bias + 64-chunk softmax.
// ---------------------------------------------------------------------------
#define BM 128
#define BN 128
#define BK 32
#define TA_BYTES (BM * 64)                       // 8192
#define TB_BYTES (BN * 64)                       // 8192
#define STG_BYTES (2 * TA_BYTES + 2 * TB_BYTES)  // 32768
#define NPIPE 3
#define GSMEM (NPIPE * STG_BYTES)                // 98304

__device__ __forceinline__ uint32_t swz(uint32_t row, uint32_t c) {
    return row * 64u + ((c ^ ((row >> 1) & 3u)) << 4);
}

template<bool ASINGLE, bool BSINGLE>
__global__ __launch_bounds__(256, 2)
void mma_gemm(const __half* __restrict__ aHi,
              const __half* __restrict__ bHi,
              const float* __restrict__ bias,
              float* __restrict__ cF32,
              __half* __restrict__ cHi,
              int Kdim, int ldc,
              size_t aPS, size_t bPS, size_t cPS,   // hi->lo plane strides
              size_t aStride, size_t bStride, size_t cStride,  // batch strides
              int do_softmax, float scale, int cSingle)
{
    extern __shared__ char smem[];
    const uint32_t sbase = smem_u32(smem);
    const int tid  = threadIdx.x;
    const int wid  = tid >> 5;
    const int lane = tid & 31;
    const int warp_m = wid & 3;          // 4 warps over M (32 rows each)
    const int warp_n = wid >> 2;         // 2 warps over N (64 cols each)
    const int rowBase = blockIdx.y * BM;
    const int colBase = blockIdx.x * BN;
    const int z = blockIdx.z;

    aHi += (size_t)z * aStride;
    bHi += (size_t)z * bStride;

    constexpr int NA = ASINGLE ? 2 : 4;  // A 16B-chunks per thread per stage
    constexpr int NB = BSINGLE ? 2 : 4;  // B 16B-chunks per thread per stage
    uint32_t goffA[NA], sdstA[NA];
    uint32_t goffB[NB], sdstB[NB];
#pragma unroll
    for (int i = 0; i < NA; ++i) {
        int q = i * 256 + tid;
        int plane = q >> 9;              // 512 chunks per plane (128 rows x 4)
        int w = q & 511;
        int row = w >> 2, c = w & 3;
        goffA[i] = (uint32_t)(plane * aPS + (size_t)(rowBase + row) * Kdim + c * 8);
        sdstA[i] = (uint32_t)(plane * TA_BYTES) + swz((uint32_t)row, (uint32_t)c);
    }
#pragma unroll
    for (int i = 0; i < NB; ++i) {
        int q = i * 256 + tid;
        int plane = q >> 9;
        int w = q & 511;
        int row = w >> 2, c = w & 3;
        goffB[i] = (uint32_t)(plane * bPS + (size_t)(colBase + row) * Kdim + c * 8);
        sdstB[i] = (uint32_t)(2 * TA_BYTES + plane * TB_BYTES) + swz((uint32_t)row, (uint32_t)c);
    }

    const int nstage = Kdim / BK;

    // prologue: stage 0 into buf 0
#pragma unroll
    for (int i = 0; i < NA; ++i) CPA16(sbase + sdstA[i], aHi + goffA[i]);
#pragma unroll
    for (int i = 0; i < NB; ++i) CPA16(sbase + sdstB[i], bHi + goffB[i]);
    CPCOMMIT();

    uint32_t aoff[2][2], boff[4][2];
#pragma unroll
    for (int m = 0; m < 2; ++m) {
        uint32_t arow = warp_m * 32 + m * 16 + (lane & 7) + ((lane >> 3) & 1) * 8;
#pragma unroll
        for (int ks = 0; ks < 2; ++ks)
            aoff[m][ks] = swz(arow, 2 * ks + (lane >> 4));
    }
#pragma unroll
    for (int p = 0; p < 4; ++p) {
        uint32_t brow = warp_n * 64 + p * 16 + (lane & 7) + ((lane >= 16) ? 8 : 0);
#pragma unroll
        for (int ks = 0; ks < 2; ++ks)
            boff[p][ks] = swz(brow, 2 * ks + ((lane >> 3) & 1));
    }

    float acc[2][8][4];
#pragma unroll
    for (int m = 0; m < 2; ++m)
#pragma unroll
        for (int n = 0; n < 8; ++n)
#pragma unroll
            for (int r = 0; r < 4; ++r) acc[m][n][r] = 0.0f;

    // main loop: load s+1 into buf (s+1)%3, wait_group 1, compute buf s%3.
    // Single barrier is skew-safe: a fast warp at iter s+1 writes buf
    // (s+2)%3 which never equals a laggard's compute buf s%3.
    for (int s = 0; s < nstage; ++s) {
        if (s + 1 < nstage) {
            uint32_t sb = sbase + ((s + 1) % 3) * STG_BYTES;
            const int koff = (s + 1) * BK;
#pragma unroll
            for (int i = 0; i < NA; ++i) CPA16(sb + sdstA[i], aHi + goffA[i] + koff);
#pragma unroll
            for (int i = 0; i < NB; ++i) CPA16(sb + sdstB[i], bHi + goffB[i] + koff);
        }
        CPCOMMIT();
        CPWAIT1();            // stage s complete (s+1's group may be in flight)
        __syncthreads();

        const uint32_t sb = sbase + (s % 3) * STG_BYTES;
#pragma unroll
        for (int ks = 0; ks < 2; ++ks) {
            uint32_t ah[2][4], al[2][4];
#pragma unroll
            for (int m = 0; m < 2; ++m) {
                LDSM4(ah[m], sb + aoff[m][ks]);
                if (!ASINGLE) LDSM4(al[m], sb + TA_BYTES + aoff[m][ks]);
            }
#pragma unroll
            for (int p = 0; p < 4; ++p) {
                uint32_t bh[4], bl[4];
                LDSM4(bh, sb + 2 * TA_BYTES + boff[p][ks]);
                if (!BSINGLE) LDSM4(bl, sb + 2 * TA_BYTES + TB_BYTES + boff[p][ks]);
#pragma unroll
                for (int m = 0; m < 2; ++m) {
#pragma unroll
                    for (int q = 0; q < 2; ++q) {
                        float* a4 = acc[m][2 * p + q];
                        MMA16816(a4, ah[m], bh[2 * q], bh[2 * q + 1]);
                        if (!BSINGLE)
                            MMA16816(a4, ah[m], bl[2 * q], bl[2 * q + 1]);
                        if (!ASINGLE)
                            MMA16816(a4, al[m], bh[2 * q], bh[2 * q + 1]);
                    }
                }
            }
        }
    }

    // ---- epilogue -------------------------------------------------------
    const int r0 = rowBase + warp_m * 32 + (lane >> 2);
    const int c0 = colBase + warp_n * 64 + (lane & 3) * 2;

    if (bias) {
#pragma unroll
        for (int n = 0; n < 8; ++n) {
            float2 bv = *(const float2*)(bias + c0 + n * 8);
#pragma unroll
            for (int m = 0; m < 2; ++m) {
                acc[m][n][0] += bv.x; acc[m][n][1] += bv.y;
                acc[m][n][2] += bv.x; acc[m][n][3] += bv.y;
            }
        }
    }
    if (do_softmax) {
#pragma unroll
        for (int m = 0; m < 2; ++m) {
#pragma unroll
            for (int hf = 0; hf < 2; ++hf) {
                float mx = -1e30f;
#pragma unroll
                for (int n = 0; n < 8; ++n)
                    mx = fmaxf(mx, fmaxf(acc[m][n][2 * hf], acc[m][n][2 * hf + 1]));
                mx = fmaxf(mx, __shfl_xor_sync(0xffffffffu, mx, 1));
                mx = fmaxf(mx, __shfl_xor_sync(0xffffffffu, mx, 2));
                float sum = 0.0f;
#pragma unroll
                for (int n = 0; n < 8; ++n) {
                    float e0 = __expf(acc[m][n][2 * hf] - mx);
                    float e1 = __expf(acc[m][n][2 * hf + 1] - mx);
                    acc[m][n][2 * hf] = e0; acc[m][n][2 * hf + 1] = e1;
                    sum += e0 + e1;
                }
                sum += __shfl_xor_sync(0xffffffffu, sum, 1);
                sum += __shfl_xor_sync(0xffffffffu, sum, 2);
                float inv = scale / sum;
#pragma unroll
                for (int n = 0; n < 8; ++n) {
                    acc[m][n][2 * hf] *= inv; acc[m][n][2 * hf + 1] *= inv;
                }
            }
        }
    }

    if (cF32) {
        float* Cb = cF32 + (size_t)z * cStride;
#pragma unroll
        for (int m = 0; m < 2; ++m) {
            const int rA = r0 + m * 16, rB = rA + 8;
#pragma unroll
            for (int n = 0; n < 8; ++n) {
                float2 v01; v01.x = acc[m][n][0]; v01.y = acc[m][n][1];
                float2 v23; v23.x = acc[m][n][2]; v23.y = acc[m][n][3];
                *(float2*)(Cb + (size_t)rA * ldc + c0 + n * 8) = v01;
                *(float2*)(Cb + (size_t)rB * ldc + c0 + n * 8) = v23;
            }
        }
    } else {
        __half* Hb = cHi + (size_t)z * cStride;
        __half* Lb = cHi + cPS + (size_t)z * cStride;
#pragma unroll
        for (int m = 0; m < 2; ++m) {
            const int rA = r0 + m * 16, rB = rA + 8;
#pragma unroll
            for (int n = 0; n < 8; ++n) {
                uint16_t h0,l0,h1,l1;
                split1(acc[m][n][0], h0, l0);
                split1(acc[m][n][1], h1, l1);
                *(uint32_t*)(Hb + (size_t)rA * ldc + c0 + n * 8) =
                    (uint32_t)h0 | ((uint32_t)h1 << 16);
                if (!cSingle)
                    *(uint32_t*)(Lb + (size_t)rA * ldc + c0 + n * 8) =
                        (uint32_t)l0 | ((uint32_t)l1 << 16);
                split1(acc[m][n][2], h0, l0);
                split1(acc[m][n][3], h1, l1);
                *(uint32_t*)(Hb + (size_t)rB * ldc + c0 + n * 8) =
                    (uint32_t)h0 | ((uint32_t)h1 << 16);
                if (!cSingle)
                    *(uint32_t*)(Lb + (size_t)rB * ldc + c0 + n * 8) =
                        (uint32_t)l0 | ((uint32_t)l1 << 16);
            }
        }
    }
}

// ---------------------------------------------------------------------------
// ctx[bh][d][e] = softmax_d( P·Wv^T + bias terms ) * scale
// ---------------------------------------------------------------------------
__global__ __launch_bounds__(256)
void ctx_kernel(const float* __restrict__ P, const float* __restrict__ Wv,
                const float* __restrict__ bk, const float* __restrict__ bv,
                const float* __restrict__ u, const float* __restrict__ w,
                float* __restrict__ ctx, float scale)
{
    __shared__ float Ps[64][33];
    __shared__ float Ws[64][33];
    __shared__ float Cm[64][65];

    const int bh = blockIdx.x;
    const int b  = bh >> 4;
    const int h  = bh & 15;
    const float* Pb  = P  + (size_t)b * DD_ + (size_t)(h * 64) * D_;
    const float* Wvb = Wv + (size_t)(h * 64) * D_;

    const int tid = threadIdx.x;
    const int dt = (tid >> 4) * 4;
    const int et = (tid & 15) * 4;
    const int lrow = tid >> 2;
    const int lc   = (tid & 3) * 8;

    float acc[4][4];
#pragma unroll
    for (int i = 0; i < 4; i++)
#pragma unroll
        for (int j = 0; j < 4; j++) acc[i][j] = 0.0f;

    for (int c0 = 0; c0 < D_; c0 += 32) {
#pragma unroll
        for (int i = 0; i < 8; ++i) {
            Ps[lrow][lc + i] = Pb [(size_t)lrow * D_ + c0 + lc + i];
            Ws[lrow][lc + i] = Wvb[(size_t)lrow * D_ + c0 + lc + i];
        }
        __syncthreads();
#pragma unroll 8
        for (int cc = 0; cc < 32; ++cc) {
            float pd[4], we[4];
#pragma unroll
            for (int i = 0; i < 4; ++i) pd[i] = Ps[dt + i][cc];
#pragma unroll
            for (int j = 0; j < 4; ++j) we[j] = Ws[et + j][cc];
#pragma unroll
            for (int i = 0; i < 4; ++i)
#pragma unroll
                for (int j = 0; j < 4; ++j)
                    acc[i][j] = fmaf(pd[i], we[j], acc[i][j]);
        }
        __syncthreads();
    }

    {
        float bkd[4], ud[4], bve[4], wze[4];
#pragma unroll
        for (int i = 0; i < 4; ++i) {
            bkd[i] = bk[h * 64 + dt + i];
            ud[i]  = u [b * D_ + h * 64 + dt + i];
        }
#pragma unroll
        for (int j = 0; j < 4; ++j) {
            bve[j] = bv[h * 64 + et + j];
            wze[j] = w [b * D_ + h * 64 + et + j];
        }
#pragma unroll
        for (int i = 0; i < 4; ++i)
#pragma unroll
            for (int j = 0; j < 4; ++j)
                acc[i][j] += ud[i] * bve[j] + bkd[i] * wze[j]
                           + (float)N_ * bkd[i] * bve[j];
    }

#pragma unroll
    for (int i = 0; i < 4; i++)
#pragma unroll
        for (int j = 0; j < 4; j++)
            Cm[dt + i][et + j] = acc[i][j];
    __syncthreads();

    if (tid < 64) {
        float m = -1e30f;
#pragma unroll 8
        for (int d = 0; d < 64; d++) m = fmaxf(m, Cm[d][tid]);
        float s = 0.0f;
#pragma unroll 8
        for (int d = 0; d < 64; d++) {
            float e = __expf(Cm[d][tid] - m);
            Cm[d][tid] = e;
            s += e;
        }
        float inv = scale / s;
        float* outp = ctx + (size_t)bh * (DH_ * DH_);
#pragma unroll 8
        for (int d = 0; d < 64; d++)
            outp[d * 64 + tid] = Cm[d][tid] * inv;
    }
}

// ---------------------------------------------------------------------------
// Vt[b][r][h64+d] = sum_e Wo[r][h64+e] * ctx[bh][d][e]  -> fp16 single plane
// ---------------------------------------------------------------------------
__global__ __launch_bounds__(256)
void vt_kernel(const float* __restrict__ ctx, const float* __restrict__ Wo,
               __half* __restrict__ vtHi)
{
    __shared__ float Cs[64][65];
    __shared__ float Wos[64][65];

    const int bh = blockIdx.x;
    const int b  = bh >> 4;
    const int h  = bh & 15;
    const int r0 = blockIdx.y * 64;
    const int tid = threadIdx.x;

    {
        int d  = tid >> 2;
        int e0 = (tid & 3) * 16;
        const float* src = ctx + (size_t)bh * 4096 + (size_t)d * 64 + e0;
#pragma unroll
        for (int i = 0; i < 16; ++i) Cs[d][e0 + i] = src[i];
        const float* ws = Wo + (size_t)(r0 + d) * D_ + h * 64 + e0;
#pragma unroll
        for (int i = 0; i < 16; ++i) Wos[d][e0 + i] = ws[i];
    }
    __syncthreads();

    const int rl = tid >> 2;
    const int dq = tid & 3;
    float acc[16];
#pragma unroll
    for (int d = 0; d < 16; ++d) acc[d] = 0.0f;

#pragma unroll 8
    for (int e = 0; e < 64; ++e) {
        float wo = Wos[rl][e];
#pragma unroll
        for (int d = 0; d < 16; ++d)
            acc[d] = fmaf(wo, Cs[dq * 16 + d][e], acc[d]);
    }

    size_t base = ((size_t)(b * D_ + r0 + rl)) * D_ + h * 64 + dq * 16;
#pragma unroll
    for (int d = 0; d < 16; d += 2) {
        uint16_t h0 = __half_as_ushort(__float2half_rn(acc[d]));
        uint16_t h1 = __half_as_ushort(__float2half_rn(acc[d + 1]));
        *(uint32_t*)(vtHi + base + d) = (uint32_t)h0 | ((uint32_t)h1 << 16);
    }
}

// ---------------------------------------------------------------------------
// Launch: two-stream fork/join overlap.
//   Stream B: Wq split, q split, splitT(v) [evV], Q-proj 1-term GEMM [evJoin]
//   Stream 0: Wk split, splitT(k), [wait evV] Gram(3t), P(3t), matvecs,
//             ctx, vt, [wait evJoin] out 1-term GEMM
// ---------------------------------------------------------------------------
extern "C" void kernel_launch(void* const* d_in, const int* in_sizes, int n_in,
                              void* d_out, int out_size)
{
    const float* q  = (const float*)d_in[0];
    const float* k  = (const float*)d_in[1];
    const float* v  = (const float*)d_in[2];
    const float* Wq = (const float*)d_in[3];
    const float* bq = (const float*)d_in[4];
    const float* Wk = (const float*)d_in[5];
    const float* bk = (const float*)d_in[6];
    const float* Wv = (const float*)d_in[7];
    const float* bv = (const float*)d_in[8];
    const float* Wo = (const float*)d_in[9];
    float* out = (float*)d_out;

    void *p_qpl, *p_qspl, *p_xkT, *p_xvT, *p_gpl, *p_wpl, *p_vtpl,
         *p_P, *p_ctx, *p_sk, *p_sv, *p_u, *p_w;
    cudaGetSymbolAddress(&p_qpl,  g_qpl);
    cudaGetSymbolAddress(&p_qspl, g_qspl);
    cudaGetSymbolAddress(&p_xkT,  g_xkT);
    cudaGetSymbolAddress(&p_xvT,  g_xvT);
    cudaGetSymbolAddress(&p_gpl,  g_gpl);
    cudaGetSymbolAddress(&p_wpl,  g_wpl);
    cudaGetSymbolAddress(&p_vtpl, g_vtpl);
    cudaGetSymbolAddress(&p_P,    g_P);
    cudaGetSymbolAddress(&p_ctx,  g_ctxm);
    cudaGetSymbolAddress(&p_sk,   g_sk);
    cudaGetSymbolAddress(&p_sv,   g_sv);
    cudaGetSymbolAddress(&p_u,    g_u);
    cudaGetSymbolAddress(&p_w,    g_w);
    __half* qpl  = (__half*)p_qpl;
    __half* qspl = (__half*)p_qspl;
    __half* xkT  = (__half*)p_xkT;
    __half* xvT  = (__half*)p_xvT;
    __half* gpl  = (__half*)p_gpl;
    __half* wpl  = (__half*)p_wpl;
    __half* vtpl = (__half*)p_vtpl;
    float* Pm   = (float*)p_P;
    float* ctxm = (float*)p_ctx;
    float* sk   = (float*)p_sk;
    float* sv   = (float*)p_sv;
    float* uu   = (float*)p_u;
    float* ww   = (float*)p_w;

    const float inv_qtr = 0.5946035575013605f;   // 8^(-1/4)

    static cudaStream_t sB = nullptr;
    static cudaEvent_t evFork = nullptr, evV = nullptr, evJoin = nullptr;
    static int inited = 0;
    if (!inited) {
        cudaFuncSetAttribute((const void*)mma_gemm<false,false>,
                             cudaFuncAttributeMaxDynamicSharedMemorySize, GSMEM);
        cudaFuncSetAttribute((const void*)mma_gemm<true,true>,
                             cudaFuncAttributeMaxDynamicSharedMemorySize, GSMEM);
        cudaStreamCreateWithFlags(&sB, cudaStreamNonBlocking);
        cudaEventCreateWithFlags(&evFork, cudaEventDisableTiming);
        cudaEventCreateWithFlags(&evV,    cudaEventDisableTiming);
        cudaEventCreateWithFlags(&evJoin, cudaEventDisableTiming);
        inited = 1;
    }

    // ---- fork -----------------------------------------------------------
    cudaEventRecord(evFork, 0);
    cudaStreamWaitEvent(sB, evFork, 0);

    // ---- stream B: Q path + splitT(v) ------------------------------------
    cudaMemsetAsync(sv, 0, 4 * D_ * sizeof(float), sB);
    split_kernel<<<512, 256, 0, sB>>>(Wq, wpl, nullptr, (int)(DD_ / 4));
    split_kernel<<<2048, 256, 0, sB>>>(q, qpl, nullptr, (int)(MD_ / 4));
    {
        dim3 tg(N_ / 32, D_ / 32, B_);
        splitT_kernel<<<tg, 256, 0, sB>>>(v, xvT, xvT + MD_, sv);
    }
    cudaEventRecord(evV, sB);
    mma_gemm<true,true><<<dim3(D_ / BN, M_ / BM, 1), 256, GSMEM, sB>>>(
        qpl, wpl, bq, nullptr, qspl,
        D_, D_, 0, 0, 0, 0, 0, MD_, 1, inv_qtr, /*cSingle=*/1);
    cudaEventRecord(evJoin, sB);

    // ---- stream 0: K path + ctx chain -------------------------------------
    cudaMemsetAsync(sk, 0, 4 * D_ * sizeof(float));
    split_kernel<<<512, 256>>>(Wk, wpl + DD_, wpl + 2 * DD_, (int)(DD_ / 4));
    {
        dim3 tg(N_ / 32, D_ / 32, B_);
        splitT_kernel<<<tg, 256>>>(k, xkT, xkT + MD_, sk);
    }
    cudaStreamWaitEvent(0, evV, 0);

    // Gram: G'[b] = Xv_b^T Xk_b  -> fp16 hi/lo planes (3-term)
    mma_gemm<false,false><<<dim3(D_ / BN, D_ / BM, B_), 256, GSMEM>>>(
        xvT, xkT, nullptr, nullptr, gpl,
        N_, D_, MD_, MD_, 4 * DD_,
        (size_t)D_ * N_, (size_t)D_ * N_, DD_, 0, 0.0f, /*cSingle=*/0);

    // P[b] = Wk (.) G'[b]  -> fp32 (3-term)
    mma_gemm<false,false><<<dim3(D_ / BN, D_ / BM, B_), 256, GSMEM>>>(
        wpl + DD_, gpl, nullptr, Pm, nullptr,
        D_, D_, DD_, 4 * DD_, 0, 0, DD_, DD_, 0, 0.0f, 0);

    // column-sum matvecs (only needed by ctx; run behind the GEMMs)
    matvec_k<<<dim3(B_, 128), 256>>>(Wk, sk, uu);
    matvec_k<<<dim3(B_, 128), 256>>>(Wv, sv, ww);

    // ctx (per b,h): P·Wv^T + bias terms, softmax over d, * scale
    ctx_kernel<<<B_ * H_, 256>>>(Pm, Wv, bk, bv, uu, ww, ctxm, inv_qtr);

    // Vt single fp16 plane
    vt_kernel<<<dim3(B_ * H_, 16), 256>>>(ctxm, Wo, vtpl);

    // ---- join, then out[b] = qs_b (.) Vt_b  (1-term) ----------------------
    cudaStreamWaitEvent(0, evJoin, 0);
    mma_gemm<true,true><<<dim3(D_ / BN, N_ / BM, B_), 256, GSMEM>>>(
        qspl, vtpl, nullptr, out, nullptr,
        D_, D_, 0, 0, 0,
        (size_t)N_ * D_, DD_, (size_t)N_ * D_, 0, 0.0f, 0);
}

// round 16
// speedup vs baseline: 1.0322x; 1.0322x over previous
#include <cuda_runtime.h>
#include <cuda_fp16.h>
#include <math.h>
#include <stdint.h>

// Problem constants
#define B_  4
#define N_  4096
#define D_  1024
#define H_  16
#define DH_ 64
#define M_  (B_ * N_)          // 16384
#define MD_ ((size_t)M_ * D_)
#define DD_ ((size_t)D_ * D_)

// ---------------------------------------------------------------------------
// Scratch (__device__ globals; no allocation allowed)
// ---------------------------------------------------------------------------
__device__ __half g_qpl [MD_];           // q single fp16 plane
__device__ __half g_qspl[MD_];           // qs single fp16 plane
__device__ __half g_xkT [2 * MD_];       // Xk^T [b][c][n] fp16 (hi | lo)
__device__ __half g_xvT [2 * MD_];       // Xv^T
__device__ __half g_gpl [2 * 4 * DD_];   // G' fp16 planes (hi | lo)
__device__ __half g_wpl [3 * DD_];       // Wq hi, Wk hi, Wk lo
__device__ __half g_vtpl[4 * DD_];       // Vt single fp16 plane
__device__ float g_P[4 * DD_];           // P[b][hd][c']
__device__ float g_ctxm[(size_t)64 * 64 * 64];
__device__ float g_sk[4 * 1024], g_sv[4 * 1024];
__device__ float g_u [4 * 1024], g_w [4 * 1024];

// ---------------------------------------------------------------------------
// PTX helpers (plain sm_103-safe)
// ---------------------------------------------------------------------------
__device__ __forceinline__ uint32_t smem_u32(const void* p) {
    uint32_t a;
    asm("{ .reg .u64 t; cvta.to.shared.u64 t, %1; cvt.u32.u64 %0, t; }"
        : "=r"(a) : "l"(p));
    return a;
}

#define CPA16(dst, src) \
    asm volatile("cp.async.cg.shared.global [%0], [%1], 16;" :: "r"(dst), "l"(src))
#define CPCOMMIT() asm volatile("cp.async.commit_group;" ::: "memory")
#define CPWAIT1()  asm volatile("cp.async.wait_group 1;" ::: "memory")

#define LDSM4(r, addr) \
    asm volatile("ldmatrix.sync.aligned.m8n8.x4.shared.b16 {%0,%1,%2,%3}, [%4];" \
        : "=r"((r)[0]), "=r"((r)[1]), "=r"((r)[2]), "=r"((r)[3]) : "r"(addr))

#define MMA16816(acc, a, b0, b1) \
    asm volatile("mma.sync.aligned.m16n8k16.row.col.f32.f16.f16.f32 " \
        "{%0,%1,%2,%3}, {%4,%5,%6,%7}, {%8,%9}, {%0,%1,%2,%3};" \
        : "+f"((acc)[0]), "+f"((acc)[1]), "+f"((acc)[2]), "+f"((acc)[3]) \
        : "r"((a)[0]), "r"((a)[1]), "r"((a)[2]), "r"((a)[3]), "r"(b0), "r"(b1))

__device__ __forceinline__ void split1(float x, uint16_t& h, uint16_t& l) {
    __half hb = __float2half_rn(x);
    __half lb = __float2half_rn(x - __half2float(hb));
    h = __half_as_ushort(hb);
    l = __half_as_ushort(lb);
}

// ---------------------------------------------------------------------------
// Row-major split: fp32 -> hi (and optional lo) fp16 planes
// ---------------------------------------------------------------------------
__global__ __launch_bounds__(256)
void split_kernel(const float* __restrict__ in,
                  __half* __restrict__ hi,
                  __half* __restrict__ lo, int n4)
{
    int i = blockIdx.x * blockDim.x + threadIdx.x;
    int stride = gridDim.x * blockDim.x;
    for (; i < n4; i += stride) {
        float4 v = ((const float4*)in)[i];
        uint16_t h0,l0,h1,l1,h2,l2,h3,l3;
        split1(v.x,h0,l0); split1(v.y,h1,l1); split1(v.z,h2,l2); split1(v.w,h3,l3);
        uint2 hv;
        hv.x = (uint32_t)h0 | ((uint32_t)h1 << 16);
        hv.y = (uint32_t)h2 | ((uint32_t)h3 << 16);
        *(uint2*)(hi + 4 * (size_t)i) = hv;
        if (lo) {
            uint2 lv;
            lv.x = (uint32_t)l0 | ((uint32_t)l1 << 16);
            lv.y = (uint32_t)l2 | ((uint32_t)l3 << 16);
            *(uint2*)(lo + 4 * (size_t)i) = lv;
        }
    }
}

// ---------------------------------------------------------------------------
// Transposing split + fused column sum:
// x[b][n][c] fp32 -> planes [b][c][n] fp16 (hi, lo); s[b][c] += sum_n x
// ---------------------------------------------------------------------------
__global__ __launch_bounds__(256)
void splitT_kernel(const float* __restrict__ in,
                   __half* __restrict__ hi,
                   __half* __restrict__ lo,
                   float* __restrict__ s)
{
    __shared__ float t[32][33];
    const int n0 = blockIdx.x * 32;
    const int c0 = blockIdx.y * 32;
    const int b  = blockIdx.z;

    {
        int row = threadIdx.x >> 3;          // n-local
        int c4  = (threadIdx.x & 7) * 4;     // c-local
        float4 v = *(const float4*)(in + ((size_t)b * N_ + n0 + row) * D_ + c0 + c4);
        t[c4 + 0][row] = v.x; t[c4 + 1][row] = v.y;
        t[c4 + 2][row] = v.z; t[c4 + 3][row] = v.w;
    }
    __syncthreads();
    {
        int c  = threadIdx.x >> 3;           // c-local
        int n4 = (threadIdx.x & 7) * 4;      // n-local
        float v0 = t[c][n4 + 0], v1 = t[c][n4 + 1];
        float v2 = t[c][n4 + 2], v3 = t[c][n4 + 3];

        float sum = (v0 + v1) + (v2 + v3);
        sum += __shfl_xor_sync(0xffffffffu, sum, 1);
        sum += __shfl_xor_sync(0xffffffffu, sum, 2);
        sum += __shfl_xor_sync(0xffffffffu, sum, 4);
        if ((threadIdx.x & 7) == 0)
            atomicAdd(&s[b * D_ + c0 + c], sum);

        uint16_t h0,l0,h1,l1,h2,l2,h3,l3;
        split1(v0, h0, l0); split1(v1, h1, l1);
        split1(v2, h2, l2); split1(v3, h3, l3);
        uint2 hv, lv;
        hv.x = (uint32_t)h0 | ((uint32_t)h1 << 16);
        hv.y = (uint32_t)h2 | ((uint32_t)h3 << 16);
        lv.x = (uint32_t)l0 | ((uint32_t)l1 << 16);
        lv.y = (uint32_t)l2 | ((uint32_t)l3 << 16);
        size_t off = ((size_t)b * D_ + c0 + c) * N_ + n0 + n4;
        *(uint2*)(hi + off) = hv;
        *(uint2*)(lo + off) = lv;
    }
}

// u[b][r] = sum_c W[r][c] * s[b][c]
__global__ __launch_bounds__(256)
void matvec_k(const float* __restrict__ W, const float* __restrict__ s,
              float* __restrict__ u)
{
    const int b = blockIdx.x;
    const int r = blockIdx.y * 8 + (threadIdx.x >> 5);
    const int lane = threadIdx.x & 31;
    float sum = 0.f;
    for (int c = lane; c < D_; c += 32)
        sum += W[(size_t)r * D_ + c] * s[b * D_ + c];
#pragma unroll
    for (int off = 16; off > 0; off >>= 1)
        sum += __shfl_xor_sync(0xffffffffu, sum, off);
    if (lane == 0) u[b * D_ + r] = sum;
}

// ---------------------------------------------------------------------------
// fp16 mma.sync GEMM, CTA tile 128x128, 256 threads (8 warps: 4M x 2N),
// warp tile 32x64, BK=32, 3-stage cp.async pipeline (lookahead-1, single
// barrier), 2 CTAs/SM. Fragment loads hoisted to break LDSM->MMA convoys.
// <ASINGLE, BSINGLE>:
//   false,false: 3-term (Ah+Al)(Bh+Bl) minus AlBl   (Gram, P)
//   true, true : 1-term Ah*Bh                       (Q-proj, out)
// Output fp32 OR fp16 plane(s) (cSingle: hi only).
// Optional fused bias + 64-chunk softmax.
// ---------------------------------------------------------------------------
#define BM 128
#define BN 128
#define BK 32
#define TA_BYTES (BM * 64)                       // 8192
#define TB_BYTES (BN * 64)                       // 8192
#define STG_BYTES (2 * TA_BYTES + 2 * TB_BYTES)  // 32768
#define NPIPE 3
#define GSMEM (NPIPE * STG_BYTES)                // 98304

__device__ __forceinline__ uint32_t swz(uint32_t row, uint32_t c) {
    return row * 64u + ((c ^ ((row >> 1) & 3u)) << 4);
}

template<bool ASINGLE, bool BSINGLE>
__global__ __launch_bounds__(256, 2)
void mma_gemm(const __half* __restrict__ aHi,
              const __half* __restrict__ bHi,
              const float* __restrict__ bias,
              float* __restrict__ cF32,
              __half* __restrict__ cHi,
              int Kdim, int ldc,
              size_t aPS, size_t bPS, size_t cPS,   // hi->lo plane strides
              size_t aStride, size_t bStride, size_t cStride,  // batch strides
              int do_softmax, float scale, int cSingle)
{
    extern __shared__ char smem[];
    const uint32_t sbase = smem_u32(smem);
    const int tid  = threadIdx.x;
    const int wid  = tid >> 5;
    const int lane = tid & 31;
    const int warp_m = wid & 3;          // 4 warps over M (32 rows each)
    const int warp_n = wid >> 2;         // 2 warps over N (64 cols each)
    const int rowBase = blockIdx.y * BM;
    const int colBase = blockIdx.x * BN;
    const int z = blockIdx.z;

    aHi += (size_t)z * aStride;
    bHi += (size_t)z * bStride;

    constexpr int NA = ASINGLE ? 2 : 4;  // A 16B-chunks per thread per stage
    constexpr int NB = BSINGLE ? 2 : 4;  // B 16B-chunks per thread per stage
    uint32_t goffA[NA], sdstA[NA];
    uint32_t goffB[NB], sdstB[NB];
#pragma unroll
    for (int i = 0; i < NA; ++i) {
        int q = i * 256 + tid;
        int plane = q >> 9;              // 512 chunks per plane (128 rows x 4)
        int w = q & 511;
        int row = w >> 2, c = w & 3;
        goffA[i] = (uint32_t)(plane * aPS + (size_t)(rowBase + row) * Kdim + c * 8);
        sdstA[i] = (uint32_t)(plane * TA_BYTES) + swz((uint32_t)row, (uint32_t)c);
    }
#pragma unroll
    for (int i = 0; i < NB; ++i) {
        int q = i * 256 + tid;
        int plane = q >> 9;
        int w = q & 511;
        int row = w >> 2, c = w & 3;
        goffB[i] = (uint32_t)(plane * bPS + (size_t)(colBase + row) * Kdim + c * 8);
        sdstB[i] = (uint32_t)(2 * TA_BYTES + plane * TB_BYTES) + swz((uint32_t)row, (uint32_t)c);
    }

    const int nstage = Kdim / BK;

    // prologue: stage 0 into buf 0
#pragma unroll
    for (int i = 0; i < NA; ++i) CPA16(sbase + sdstA[i], aHi + goffA[i]);
#pragma unroll
    for (int i = 0; i < NB; ++i) CPA16(sbase + sdstB[i], bHi + goffB[i]);
    CPCOMMIT();

    uint32_t aoff[2][2], boff[4][2];
#pragma unroll
    for (int m = 0; m < 2; ++m) {
        uint32_t arow = warp_m * 32 + m * 16 + (lane & 7) + ((lane >> 3) & 1) * 8;
#pragma unroll
        for (int ks = 0; ks < 2; ++ks)
            aoff[m][ks] = swz(arow, 2 * ks + (lane >> 4));
    }
#pragma unroll
    for (int p = 0; p < 4; ++p) {
        uint32_t brow = warp_n * 64 + p * 16 + (lane & 7) + ((lane >= 16) ? 8 : 0);
#pragma unroll
        for (int ks = 0; ks < 2; ++ks)
            boff[p][ks] = swz(brow, 2 * ks + ((lane >> 3) & 1));
    }

    float acc[2][8][4];
#pragma unroll
    for (int m = 0; m < 2; ++m)
#pragma unroll
        for (int n = 0; n < 8; ++n)
#pragma unroll
            for (int r = 0; r < 4; ++r) acc[m][n][r] = 0.0f;

    // main loop: load s+1 into buf (s+1)%3, wait_group 1, compute buf s%3.
    for (int s = 0; s < nstage; ++s) {
        if (s + 1 < nstage) {
            uint32_t sb = sbase + ((s + 1) % 3) * STG_BYTES;
            const int koff = (s + 1) * BK;
#pragma unroll
            for (int i = 0; i < NA; ++i) CPA16(sb + sdstA[i], aHi + goffA[i] + koff);
#pragma unroll
            for (int i = 0; i < NB; ++i) CPA16(sb + sdstB[i], bHi + goffB[i] + koff);
        }
        CPCOMMIT();
        CPWAIT1();            // stage s complete (s+1's group may be in flight)
        __syncthreads();

        const uint32_t sb = sbase + (s % 3) * STG_BYTES;

        if (ASINGLE && BSINGLE) {
            // 1-term: hoist the ENTIRE stage's fragments (12 LDSM4 = 48 regs),
            // then run 64 MMAs back-to-back.
            uint32_t ah2[2][2][4], bh2[2][4][4];
#pragma unroll
            for (int ks = 0; ks < 2; ++ks) {
#pragma unroll
                for (int m = 0; m < 2; ++m)
                    LDSM4(ah2[ks][m], sb + aoff[m][ks]);
#pragma unroll
                for (int p = 0; p < 4; ++p)
                    LDSM4(bh2[ks][p], sb + 2 * TA_BYTES + boff[p][ks]);
            }
#pragma unroll
            for (int ks = 0; ks < 2; ++ks)
#pragma unroll
                for (int p = 0; p < 4; ++p)
#pragma unroll
                    for (int m = 0; m < 2; ++m)
#pragma unroll
                        for (int q = 0; q < 2; ++q)
                            MMA16816(acc[m][2 * p + q], ah2[ks][m],
                                     bh2[ks][p][2 * q], bh2[ks][p][2 * q + 1]);
        } else {
            // 3-term: per ks, hoist all A and all B fragments (12 LDSM4),
            // then 48 MMAs back-to-back.
#pragma unroll
            for (int ks = 0; ks < 2; ++ks) {
                uint32_t ah[2][4], al[2][4], bh4[4][4], bl4[4][4];
#pragma unroll
                for (int m = 0; m < 2; ++m) {
                    LDSM4(ah[m], sb + aoff[m][ks]);
                    LDSM4(al[m], sb + TA_BYTES + aoff[m][ks]);
                }
#pragma unroll
                for (int p = 0; p < 4; ++p) {
                    LDSM4(bh4[p], sb + 2 * TA_BYTES + boff[p][ks]);
                    LDSM4(bl4[p], sb + 2 * TA_BYTES + TB_BYTES + boff[p][ks]);
                }
#pragma unroll
                for (int p = 0; p < 4; ++p)
#pragma unroll
                    for (int m = 0; m < 2; ++m)
#pragma unroll
                        for (int q = 0; q < 2; ++q) {
                            float* a4 = acc[m][2 * p + q];
                            MMA16816(a4, ah[m], bh4[p][2 * q], bh4[p][2 * q + 1]);
                            MMA16816(a4, ah[m], bl4[p][2 * q], bl4[p][2 * q + 1]);
                            MMA16816(a4, al[m], bh4[p][2 * q], bh4[p][2 * q + 1]);
                        }
            }
        }
    }

    // ---- epilogue -------------------------------------------------------
    const int r0 = rowBase + warp_m * 32 + (lane >> 2);
    const int c0 = colBase + warp_n * 64 + (lane & 3) * 2;

    if (bias) {
#pragma unroll
        for (int n = 0; n < 8; ++n) {
            float2 bv = *(const float2*)(bias + c0 + n * 8);
#pragma unroll
            for (int m = 0; m < 2; ++m) {
                acc[m][n][0] += bv.x; acc[m][n][1] += bv.y;
                acc[m][n][2] += bv.x; acc[m][n][3] += bv.y;
            }
        }
    }
    if (do_softmax) {
#pragma unroll
        for (int m = 0; m < 2; ++m) {
#pragma unroll
            for (int hf = 0; hf < 2; ++hf) {
                float mx = -1e30f;
#pragma unroll
                for (int n = 0; n < 8; ++n)
                    mx = fmaxf(mx, fmaxf(acc[m][n][2 * hf], acc[m][n][2 * hf + 1]));
                mx = fmaxf(mx, __shfl_xor_sync(0xffffffffu, mx, 1));
                mx = fmaxf(mx, __shfl_xor_sync(0xffffffffu, mx, 2));
                float sum = 0.0f;
#pragma unroll
                for (int n = 0; n < 8; ++n) {
                    float e0 = __expf(acc[m][n][2 * hf] - mx);
                    float e1 = __expf(acc[m][n][2 * hf + 1] - mx);
                    acc[m][n][2 * hf] = e0; acc[m][n][2 * hf + 1] = e1;
                    sum += e0 + e1;
                }
                sum += __shfl_xor_sync(0xffffffffu, sum, 1);
                sum += __shfl_xor_sync(0xffffffffu, sum, 2);
                float inv = scale / sum;
#pragma unroll
                for (int n = 0; n < 8; ++n) {
                    acc[m][n][2 * hf] *= inv; acc[m][n][2 * hf + 1] *= inv;
                }
            }
        }
    }

    if (cF32) {
        float* Cb = cF32 + (size_t)z * cStride;
#pragma unroll
        for (int m = 0; m < 2; ++m) {
            const int rA = r0 + m * 16, rB = rA + 8;
#pragma unroll
            for (int n = 0; n < 8; ++n) {
                float2 v01; v01.x = acc[m][n][0]; v01.y = acc[m][n][1];
                float2 v23; v23.x = acc[m][n][2]; v23.y = acc[m][n][3];
                *(float2*)(Cb + (size_t)rA * ldc + c0 + n * 8) = v01;
                *(float2*)(Cb + (size_t)rB * ldc + c0 + n * 8) = v23;
            }
        }
    } else {
        __half* Hb = cHi + (size_t)z * cStride;
        __half* Lb = cHi + cPS + (size_t)z * cStride;
#pragma unroll
        for (int m = 0; m < 2; ++m) {
            const int rA = r0 + m * 16, rB = rA + 8;
#pragma unroll
            for (int n = 0; n < 8; ++n) {
                uint16_t h0,l0,h1,l1;
                split1(acc[m][n][0], h0, l0);
                split1(acc[m][n][1], h1, l1);
                *(uint32_t*)(Hb + (size_t)rA * ldc + c0 + n * 8) =
                    (uint32_t)h0 | ((uint32_t)h1 << 16);
                if (!cSingle)
                    *(uint32_t*)(Lb + (size_t)rA * ldc + c0 + n * 8) =
                        (uint32_t)l0 | ((uint32_t)l1 << 16);
                split1(acc[m][n][2], h0, l0);
                split1(acc[m][n][3], h1, l1);
                *(uint32_t*)(Hb + (size_t)rB * ldc + c0 + n * 8) =
                    (uint32_t)h0 | ((uint32_t)h1 << 16);
                if (!cSingle)
                    *(uint32_t*)(Lb + (size_t)rB * ldc + c0 + n * 8) =
                        (uint32_t)l0 | ((uint32_t)l1 << 16);
            }
        }
    }
}

// ---------------------------------------------------------------------------
// ctx[bh][d][e] = softmax_d( P·Wv^T + bias terms ) * scale
// ---------------------------------------------------------------------------
__global__ __launch_bounds__(256)
void ctx_kernel(const float* __restrict__ P, const float* __restrict__ Wv,
                const float* __restrict__ bk, const float* __restrict__ bv,
                const float* __restrict__ u, const float* __restrict__ w,
                float* __restrict__ ctx, float scale)
{
    __shared__ float Ps[64][33];
    __shared__ float Ws[64][33];
    __shared__ float Cm[64][65];

    const int bh = blockIdx.x;
    const int b  = bh >> 4;
    const int h  = bh & 15;
    const float* Pb  = P  + (size_t)b * DD_ + (size_t)(h * 64) * D_;
    const float* Wvb = Wv + (size_t)(h * 64) * D_;

    const int tid = threadIdx.x;
    const int dt = (tid >> 4) * 4;
    const int et = (tid & 15) * 4;
    const int lrow = tid >> 2;
    const int lc   = (tid & 3) * 8;

    float acc[4][4];
#pragma unroll
    for (int i = 0; i < 4; i++)
#pragma unroll
        for (int j = 0; j < 4; j++) acc[i][j] = 0.0f;

    for (int c0 = 0; c0 < D_; c0 += 32) {
#pragma unroll
        for (int i = 0; i < 8; ++i) {
            Ps[lrow][lc + i] = Pb [(size_t)lrow * D_ + c0 + lc + i];
            Ws[lrow][lc + i] = Wvb[(size_t)lrow * D_ + c0 + lc + i];
        }
        __syncthreads();
#pragma unroll 8
        for (int cc = 0; cc < 32; ++cc) {
            float pd[4], we[4];
#pragma unroll
            for (int i = 0; i < 4; ++i) pd[i] = Ps[dt + i][cc];
#pragma unroll
            for (int j = 0; j < 4; ++j) we[j] = Ws[et + j][cc];
#pragma unroll
            for (int i = 0; i < 4; ++i)
#pragma unroll
                for (int j = 0; j < 4; ++j)
                    acc[i][j] = fmaf(pd[i], we[j], acc[i][j]);
        }
        __syncthreads();
    }

    {
        float bkd[4], ud[4], bve[4], wze[4];
#pragma unroll
        for (int i = 0; i < 4; ++i) {
            bkd[i] = bk[h * 64 + dt + i];
            ud[i]  = u [b * D_ + h * 64 + dt + i];
        }
#pragma unroll
        for (int j = 0; j < 4; ++j) {
            bve[j] = bv[h * 64 + et + j];
            wze[j] = w [b * D_ + h * 64 + et + j];
        }
#pragma unroll
        for (int i = 0; i < 4; ++i)
#pragma unroll
            for (int j = 0; j < 4; ++j)
                acc[i][j] += ud[i] * bve[j] + bkd[i] * wze[j]
                           + (float)N_ * bkd[i] * bve[j];
    }

#pragma unroll
    for (int i = 0; i < 4; i++)
#pragma unroll
        for (int j = 0; j < 4; j++)
            Cm[dt + i][et + j] = acc[i][j];
    __syncthreads();

    if (tid < 64) {
        float m = -1e30f;
#pragma unroll 8
        for (int d = 0; d < 64; d++) m = fmaxf(m, Cm[d][tid]);
        float s = 0.0f;
#pragma unroll 8
        for (int d = 0; d < 64; d++) {
            float e = __expf(Cm[d][tid] - m);
            Cm[d][tid] = e;
            s += e;
        }
        float inv = scale / s;
        float* outp = ctx + (size_t)bh * (DH_ * DH_);
#pragma unroll 8
        for (int d = 0; d < 64; d++)
            outp[d * 64 + tid] = Cm[d][tid] * inv;
    }
}

// ---------------------------------------------------------------------------
// Vt[b][r][h64+d] = sum_e Wo[r][h64+e] * ctx[bh][d][e]  -> fp16 single plane
// ---------------------------------------------------------------------------
__global__ __launch_bounds__(256)
void vt_kernel(const float* __restrict__ ctx, const float* __restrict__ Wo,
               __half* __restrict__ vtHi)
{
    __shared__ float Cs[64][65];
    __shared__ float Wos[64][65];

    const int bh = blockIdx.x;
    const int b  = bh >> 4;
    const int h  = bh & 15;
    const int r0 = blockIdx.y * 64;
    const int tid = threadIdx.x;

    {
        int d  = tid >> 2;
        int e0 = (tid & 3) * 16;
        const float* src = ctx + (size_t)bh * 4096 + (size_t)d * 64 + e0;
#pragma unroll
        for (int i = 0; i < 16; ++i) Cs[d][e0 + i] = src[i];
        const float* ws = Wo + (size_t)(r0 + d) * D_ + h * 64 + e0;
#pragma unroll
        for (int i = 0; i < 16; ++i) Wos[d][e0 + i] = ws[i];
    }
    __syncthreads();

    const int rl = tid >> 2;
    const int dq = tid & 3;
    float acc[16];
#pragma unroll
    for (int d = 0; d < 16; ++d) acc[d] = 0.0f;

#pragma unroll 8
    for (int e = 0; e < 64; ++e) {
        float wo = Wos[rl][e];
#pragma unroll
        for (int d = 0; d < 16; ++d)
            acc[d] = fmaf(wo, Cs[dq * 16 + d][e], acc[d]);
    }

    size_t base = ((size_t)(b * D_ + r0 + rl)) * D_ + h * 64 + dq * 16;
#pragma unroll
    for (int d = 0; d < 16; d += 2) {
        uint16_t h0 = __half_as_ushort(__float2half_rn(acc[d]));
        uint16_t h1 = __half_as_ushort(__float2half_rn(acc[d + 1]));
        *(uint32_t*)(vtHi + base + d) = (uint32_t)h0 | ((uint32_t)h1 << 16);
    }
}

// ---------------------------------------------------------------------------
// Launch: two-stream fork/join overlap.
//   Stream B: Wq split, q split, splitT(v) [evV], Q-proj 1-term GEMM [evJoin]
//   Stream 0: Wk split, splitT(k), [wait evV] Gram(3t), P(3t), matvecs,
//             ctx, vt, [wait evJoin] out 1-term GEMM
// ---------------------------------------------------------------------------
extern "C" void kernel_launch(void* const* d_in, const int* in_sizes, int n_in,
                              void* d_out, int out_size)
{
    const float* q  = (const float*)d_in[0];
    const float* k  = (const float*)d_in[1];
    const float* v  = (const float*)d_in[2];
    const float* Wq = (const float*)d_in[3];
    const float* bq = (const float*)d_in[4];
    const float* Wk = (const float*)d_in[5];
    const float* bk = (const float*)d_in[6];
    const float* Wv = (const float*)d_in[7];
    const float* bv = (const float*)d_in[8];
    const float* Wo = (const float*)d_in[9];
    float* out = (float*)d_out;

    void *p_qpl, *p_qspl, *p_xkT, *p_xvT, *p_gpl, *p_wpl, *p_vtpl,
         *p_P, *p_ctx, *p_sk, *p_sv, *p_u, *p_w;
    cudaGetSymbolAddress(&p_qpl,  g_qpl);
    cudaGetSymbolAddress(&p_qspl, g_qspl);
    cudaGetSymbolAddress(&p_xkT,  g_xkT);
    cudaGetSymbolAddress(&p_xvT,  g_xvT);
    cudaGetSymbolAddress(&p_gpl,  g_gpl);
    cudaGetSymbolAddress(&p_wpl,  g_wpl);
    cudaGetSymbolAddress(&p_vtpl, g_vtpl);
    cudaGetSymbolAddress(&p_P,    g_P);
    cudaGetSymbolAddress(&p_ctx,  g_ctxm);
    cudaGetSymbolAddress(&p_sk,   g_sk);
    cudaGetSymbolAddress(&p_sv,   g_sv);
    cudaGetSymbolAddress(&p_u,    g_u);
    cudaGetSymbolAddress(&p_w,    g_w);
    __half* qpl  = (__half*)p_qpl;
    __half* qspl = (__half*)p_qspl;
    __half* xkT  = (__half*)p_xkT;
    __half* xvT  = (__half*)p_xvT;
    __half* gpl  = (__half*)p_gpl;
    __half* wpl  = (__half*)p_wpl;
    __half* vtpl = (__half*)p_vtpl;
    float* Pm   = (float*)p_P;
    float* ctxm = (float*)p_ctx;
    float* sk   = (float*)p_sk;
    float* sv   = (float*)p_sv;
    float* uu   = (float*)p_u;
    float* ww   = (float*)p_w;

    const float inv_qtr = 0.5946035575013605f;   // 8^(-1/4)

    static cudaStream_t sB = nullptr;
    static cudaEvent_t evFork = nullptr, evV = nullptr, evJoin = nullptr;
    static int inited = 0;
    if (!inited) {
        cudaFuncSetAttribute((const void*)mma_gemm<false,false>,
                             cudaFuncAttributeMaxDynamicSharedMemorySize, GSMEM);
        cudaFuncSetAttribute((const void*)mma_gemm<true,true>,
                             cudaFuncAttributeMaxDynamicSharedMemorySize, GSMEM);
        cudaStreamCreateWithFlags(&sB, cudaStreamNonBlocking);
        cudaEventCreateWithFlags(&evFork, cudaEventDisableTiming);
        cudaEventCreateWithFlags(&evV,    cudaEventDisableTiming);
        cudaEventCreateWithFlags(&evJoin, cudaEventDisableTiming);
        inited = 1;
    }

    // ---- fork -----------------------------------------------------------
    cudaEventRecord(evFork, 0);
    cudaStreamWaitEvent(sB, evFork, 0);

    // ---- stream B: Q path + splitT(v) ------------------------------------
    cudaMemsetAsync(sv, 0, 4 * D_ * sizeof(float), sB);
    split_kernel<<<512, 256, 0, sB>>>(Wq, wpl, nullptr, (int)(DD_ / 4));
    split_kernel<<<2048, 256, 0, sB>>>(q, qpl, nullptr, (int)(MD_ / 4));
    {
        dim3 tg(N_ / 32, D_ / 32, B_);
        splitT_kernel<<<tg, 256, 0, sB>>>(v, xvT, xvT + MD_, sv);
    }
    cudaEventRecord(evV, sB);
    mma_gemm<true,true><<<dim3(D_ / BN, M_ / BM, 1), 256, GSMEM, sB>>>(
        qpl, wpl, bq, nullptr, qspl,
        D_, D_, 0, 0, 0, 0, 0, MD_, 1, inv_qtr, /*cSingle=*/1);
    cudaEventRecord(evJoin, sB);

    // ---- stream 0: K path + ctx chain -------------------------------------
    cudaMemsetAsync(sk, 0, 4 * D_ * sizeof(float));
    split_kernel<<<512, 256>>>(Wk, wpl + DD_, wpl + 2 * DD_, (int)(DD_ / 4));
    {
        dim3 tg(N_ / 32, D_ / 32, B_);
        splitT_kernel<<<tg, 256>>>(k, xkT, xkT + MD_, sk);
    }
    cudaStreamWaitEvent(0, evV, 0);

    // Gram: G'[b] = Xv_b^T Xk_b  -> fp16 hi/lo planes (3-term)
    mma_gemm<false,false><<<dim3(D_ / BN, D_ / BM, B_), 256, GSMEM>>>(
        xvT, xkT, nullptr, nullptr, gpl,
        N_, D_, MD_, MD_, 4 * DD_,
        (size_t)D_ * N_, (size_t)D_ * N_, DD_, 0, 0.0f, /*cSingle=*/0);

    // P[b] = Wk (.) G'[b]  -> fp32 (3-term)
    mma_gemm<false,false><<<dim3(D_ / BN, D_ / BM, B_), 256, GSMEM>>>(
        wpl + DD_, gpl, nullptr, Pm, nullptr,
        D_, D_, DD_, 4 * DD_, 0, 0, DD_, DD_, 0, 0.0f, 0);

    // column-sum matvecs (only needed by ctx; run behind the GEMMs)
    matvec_k<<<dim3(B_, 128), 256>>>(Wk, sk, uu);
    matvec_k<<<dim3(B_, 128), 256>>>(Wv, sv, ww);

    // ctx (per b,h): P·Wv^T + bias terms, softmax over d, * scale
    ctx_kernel<<<B_ * H_, 256>>>(Pm, Wv, bk, bv, uu, ww, ctxm, inv_qtr);

    // Vt single fp16 plane
    vt_kernel<<<dim3(B_ * H_, 16), 256>>>(ctxm, Wo, vtpl);

    // ---- join, then out[b] = qs_b (.) Vt_b  (1-term) ----------------------
    cudaStreamWaitEvent(0, evJoin, 0);
    mma_gemm<true,true><<<dim3(D_ / BN, N_ / BM, B_), 256, GSMEM>>>(
        qspl, vtpl, nullptr, out, nullptr,
        D_, D_, 0, 0, 0,
        (size_t)N_ * D_, DD_, (size_t)N_ * D_, 0, 0.0f, 0);
}